// round 17
// baseline (speedup 1.0000x reference)
#include <cuda_runtime.h>
#include <cuda_bf16.h>
#include <cstdint>

// Problem constants (fixed by the dataset)
#define NNODES 20000
#define NEDGES 256000
#define HD     128
#define NR     100
#define NB     64
#define NQ     2048   // B query pairs

// ---------------- scratch (no allocation allowed) ----------------
__device__ float g_out1[NNODES * HD];        // layer1 pre-activation
__device__ float g_out2[NNODES * 2 * HD];    // layer2 output
__device__ float g_z[NNODES * HD];           // latent (fp32, for hr gather)
__device__ __nv_bfloat16 g_z_hi[NNODES * HD];
__device__ __nv_bfloat16 g_z_lo[NNODES * HD];
__device__ __nv_bfloat16 g_hr_hi[NQ * HD];
__device__ __nv_bfloat16 g_hr_lo[NQ * HD];

// ---------------- vectorized global reduction -------------------
__device__ __forceinline__ void red_add_v4(float* p, float a, float b, float c, float d) {
    asm volatile("red.global.v4.f32.add [%0], {%1,%2,%3,%4};"
                 :: "l"(p), "f"(a), "f"(b), "f"(c), "f"(d) : "memory");
}

__device__ __forceinline__ uint32_t smem_to_u32(const void* p) {
    uint32_t a;
    asm("{ .reg .u64 t; cvta.to.shared.u64 t, %1; cvt.u32.u64 %0, t; }" : "=r"(a) : "l"(p));
    return a;
}

// ldmatrix x4 (no trans)
__device__ __forceinline__ void ldsm_x4(uint32_t addr, uint32_t* r) {
    asm volatile("ldmatrix.sync.aligned.m8n8.x4.shared.b16 {%0,%1,%2,%3}, [%4];"
                 : "=r"(r[0]), "=r"(r[1]), "=r"(r[2]), "=r"(r[3]) : "r"(addr));
}
// bf16 mma: D(f32) += A(bf16) * B(bf16)
__device__ __forceinline__ void mma_bf16(float* c, const uint32_t* a, const uint32_t* b) {
    asm volatile(
        "mma.sync.aligned.m16n8k16.row.col.f32.bf16.bf16.f32 "
        "{%0,%1,%2,%3}, {%4,%5,%6,%7}, {%8,%9}, {%0,%1,%2,%3};"
        : "+f"(c[0]), "+f"(c[1]), "+f"(c[2]), "+f"(c[3])
        : "r"(a[0]), "r"(a[1]), "r"(a[2]), "r"(a[3]), "r"(b[0]), "r"(b[1]));
}

// bf16 split: x = hi + lo (hi = rn(x), lo = rn(x - hi))
__device__ __forceinline__ void split_bf16(float x, __nv_bfloat16& hi, __nv_bfloat16& lo) {
    hi = __float2bfloat16(x);
    lo = __float2bfloat16(x - __bfloat162float(hi));
}

// ================= self-loop layer 1: out1 = X@lw1 + b1 =========
__global__ void selfloop1_kernel(const float* __restrict__ embed,
                                 const int* __restrict__ h,
                                 const float* __restrict__ lw1,
                                 const float* __restrict__ b1) {
    __shared__ float xs[8][HD];
    int t = threadIdx.x;
    int n0 = blockIdx.x * 8;
#pragma unroll
    for (int nb = 0; nb < 8; nb++) {
        int node = n0 + nb;
        xs[nb][t] = embed[(size_t)h[node] * HD + t];
    }
    __syncthreads();
    float acc[8] = {0,0,0,0,0,0,0,0};
#pragma unroll 4
    for (int k = 0; k < HD; k++) {
        float w = lw1[k * HD + t];
#pragma unroll
        for (int nb = 0; nb < 8; nb++) acc[nb] = fmaf(xs[nb][k], w, acc[nb]);
    }
    float bias = b1[t];
#pragma unroll
    for (int nb = 0; nb < 8; nb++)
        g_out1[(size_t)(n0 + nb) * HD + t] = acc[nb] + bias;
}

// ====== edge layer 1: weights in smem (swizzled), coalesced edges
// W1 per rel = 256 floats = 64 float4. Lane l owns float4s l*2..l*2+1.
// Store: logical chunk k of lane lc at physical slot k ^ ((lc>>2)&1).
// Read lane l, slot j^k0 -> holds logical (j^k0)^k0 = j. NO extra swap.
__global__ __launch_bounds__(512) void edge1_kernel(
        const float* __restrict__ embed,
        const int* __restrict__ h,
        const int* __restrict__ src,
        const int* __restrict__ dst,
        const int* __restrict__ et,
        const float* __restrict__ norm,
        const float* __restrict__ W1) {
    extern __shared__ float4 swq[];           // 6400 float4 = 102400 B
    for (int f = threadIdx.x; f < NR * 64; f += 512) {
        int r = f >> 6, fr = f & 63, lc = fr >> 1, k = fr & 1;
        swq[(r << 6) + (lc << 1) + (k ^ ((lc >> 2) & 1))] = ((const float4*)W1)[f];
    }
    __syncthreads();
    int l = threadIdx.x & 31;
    int k0 = (l >> 2) & 1;
    int gw = (blockIdx.x * 512 + threadIdx.x) >> 5;
    int nw = (gridDim.x * 512) >> 5;
    for (int e0 = gw * 4; e0 < NEDGES; e0 += nw * 4) {
        int s[4], d[4], r[4];
        float nr[4];
#pragma unroll
        for (int i = 0; i < 4; i++) {
            int e = e0 + i;
            s[i] = src[e]; d[i] = dst[e]; r[i] = et[e]; nr[i] = norm[e];
        }
        int hs[4];
#pragma unroll
        for (int i = 0; i < 4; i++) hs[i] = h[s[i]];
        float4 xv[4];
#pragma unroll
        for (int i = 0; i < 4; i++)
            xv[i] = *(const float4*)(embed + (size_t)hs[i] * HD + 4 * l);
#pragma unroll
        for (int i = 0; i < 4; i++) {
            const float4* wp = swq + (r[i] << 6) + (l << 1);
            float4 w0 = wp[0 ^ k0];   // logical chunk 0 (block 2l)
            float4 w1 = wp[1 ^ k0];   // logical chunk 1 (block 2l+1)
            float m0 = (xv[i].x * w0.x + xv[i].y * w0.z) * nr[i];
            float m1 = (xv[i].x * w0.y + xv[i].y * w0.w) * nr[i];
            float m2 = (xv[i].z * w1.x + xv[i].w * w1.z) * nr[i];
            float m3 = (xv[i].z * w1.y + xv[i].w * w1.w) * nr[i];
            red_add_v4(g_out1 + (size_t)d[i] * HD + 4 * l, m0, m1, m2, m3);
        }
    }
}

// ================= self-loop layer 2: out2 = relu(out1)@lw2 + b2
__global__ void selfloop2_kernel(const float* __restrict__ lw2,
                                 const float* __restrict__ b2) {
    __shared__ float xs[4][HD];
    int t = threadIdx.x;
    int n0 = blockIdx.x * 4;
    for (int idx = t; idx < 4 * HD; idx += 256) {
        int nb = idx >> 7, k = idx & 127;
        float v = g_out1[(size_t)(n0 + nb) * HD + k];
        xs[nb][k] = v > 0.f ? v : 0.f;
    }
    __syncthreads();
    float acc[4] = {0,0,0,0};
#pragma unroll 4
    for (int k = 0; k < HD; k++) {
        float w = lw2[k * 256 + t];
#pragma unroll
        for (int nb = 0; nb < 4; nb++) acc[nb] = fmaf(xs[nb][k], w, acc[nb]);
    }
    float bias = b2[t];
#pragma unroll
    for (int nb = 0; nb < 4; nb++)
        g_out2[(size_t)(n0 + nb) * 256 + t] = acc[nb] + bias;
}

// ====== edge layer 2: weights in smem (swizzled), coalesced edges
// W2 per rel = 512 floats = 128 float4. Lane l owns float4s l*4..l*4+3.
// Store: logical chunk k of lane lc at physical slot k ^ ((lc>>1)&3).
// Read lane l, slot j^k0 -> logical j. (q_j IS logical chunk j.)
__global__ __launch_bounds__(512) void edge2_kernel(
        const int* __restrict__ src,
        const int* __restrict__ dst,
        const int* __restrict__ et,
        const float* __restrict__ norm,
        const float* __restrict__ W2) {
    extern __shared__ float4 swq[];           // 12800 float4 = 204800 B
    for (int f = threadIdx.x; f < NR * 128; f += 512) {
        int r = f >> 7, fr = f & 127, lc = fr >> 2, k = fr & 3;
        swq[(r << 7) + (lc << 2) + (k ^ ((lc >> 1) & 3))] = ((const float4*)W2)[f];
    }
    __syncthreads();
    int l = threadIdx.x & 31;
    int k0 = (l >> 1) & 3;
    int gw = (blockIdx.x * 512 + threadIdx.x) >> 5;
    int nw = (gridDim.x * 512) >> 5;
    for (int e0 = gw * 4; e0 < NEDGES; e0 += nw * 4) {
        int s[4], d[4], r[4];
        float nr[4];
#pragma unroll
        for (int i = 0; i < 4; i++) {
            int e = e0 + i;
            s[i] = src[e]; d[i] = dst[e]; r[i] = et[e]; nr[i] = norm[e];
        }
        float4 xv[4];
#pragma unroll
        for (int i = 0; i < 4; i++) {
            float4 v = *(const float4*)(g_out1 + (size_t)s[i] * HD + 4 * l);
            v.x = v.x > 0.f ? v.x : 0.f;
            v.y = v.y > 0.f ? v.y : 0.f;
            v.z = v.z > 0.f ? v.z : 0.f;
            v.w = v.w > 0.f ? v.w : 0.f;
            xv[i] = v;
        }
#pragma unroll
        for (int i = 0; i < 4; i++) {
            const float4* wp = swq + (r[i] << 7) + (l << 2);
            float4 wa0 = wp[0 ^ k0];   // logical chunk 0: block 2l,   i=0
            float4 wa1 = wp[1 ^ k0];   // logical chunk 1: block 2l,   i=1
            float4 wb0 = wp[2 ^ k0];   // logical chunk 2: block 2l+1, i=0
            float4 wb1 = wp[3 ^ k0];   // logical chunk 3: block 2l+1, i=1
            float m0 = (xv[i].x * wa0.x + xv[i].y * wa1.x) * nr[i];
            float m1 = (xv[i].x * wa0.y + xv[i].y * wa1.y) * nr[i];
            float m2 = (xv[i].x * wa0.z + xv[i].y * wa1.z) * nr[i];
            float m3 = (xv[i].x * wa0.w + xv[i].y * wa1.w) * nr[i];
            float m4 = (xv[i].z * wb0.x + xv[i].w * wb1.x) * nr[i];
            float m5 = (xv[i].z * wb0.y + xv[i].w * wb1.y) * nr[i];
            float m6 = (xv[i].z * wb0.z + xv[i].w * wb1.z) * nr[i];
            float m7 = (xv[i].z * wb0.w + xv[i].w * wb1.w) * nr[i];
            float* p = g_out2 + (size_t)d[i] * 256 + 8 * l;
            red_add_v4(p,     m0, m1, m2, m3);
            red_add_v4(p + 4, m4, m5, m6, m7);
        }
    }
}

// ====== z = m + sqrt(softplus(hv)+1e-8)*eps; also split to bf16 ==
__global__ void z_kernel(const float* __restrict__ eps) {
    int i = blockIdx.x * blockDim.x + threadIdx.x;   // over N*HD
    if (i >= NNODES * HD) return;
    int n = i >> 7, j = i & 127;
    float m  = g_out2[(size_t)n * 256 + j];
    float hv = g_out2[(size_t)n * 256 + 128 + j];
    float sp = fmaxf(hv, 0.f) + log1pf(expf(-fabsf(hv)));
    float v = sp + 1e-8f;
    float z = fmaf(sqrtf(v), eps[i], m);
    g_z[i] = z;
    __nv_bfloat16 hi, lo;
    split_bf16(z, hi, lo);
    g_z_hi[i] = hi;
    g_z_lo[i] = lo;
}

// ====== hr = z[head] * w_rel[rel], split to bf16 ================
__global__ void hr_kernel(const int* __restrict__ head_ids,
                          const int* __restrict__ rel_ids,
                          const float* __restrict__ w_rel) {
    int i = blockIdx.x * blockDim.x + threadIdx.x;   // over NQ*HD
    if (i >= NQ * HD) return;
    int b = i >> 7, j = i & 127;
    float hr = g_z[(size_t)head_ids[b] * HD + j] * w_rel[(size_t)rel_ids[b] * HD + j];
    __nv_bfloat16 hi, lo;
    split_bf16(hr, hi, lo);
    g_hr_hi[i] = hi;
    g_hr_lo[i] = lo;
}

// ================= scores = hr @ z^T via mma.sync (bf16 split) ==
// Tile 128x128 per CTA, 8 warps (2x4), warp tile 64x32, K=128 resident.
// smem rows padded to 136 bf16 (272B): ldmatrix conflict-free.
#define TM 128
#define TN 128
#define PAD_K   136
#define TILE_B  (128 * PAD_K * 2)          // 34816 bytes per buffer
#define S2_A_HI 0
#define S2_A_LO (S2_A_HI + TILE_B)
#define S2_B_HI (S2_A_LO + TILE_B)
#define S2_B_LO (S2_B_HI + TILE_B)
#define S2_TOTAL (4 * TILE_B)              // 139264 bytes

__global__ __launch_bounds__(256, 1) void scores_mma_kernel(float* __restrict__ C) {
    extern __shared__ char smem[];
    uint32_t sb = smem_to_u32(smem);
    int tid = threadIdx.x;
    int wid = tid >> 5, lid = tid & 31;
    int m0 = blockIdx.y * TM;
    int n0 = blockIdx.x * TN;

    // ---- stage tiles gmem(bf16) -> smem (padded rows) ----
    for (int u = tid; u < 2048; u += 256) {
        int row = u >> 4, ch = u & 15;
        uint32_t so = (uint32_t)row * (PAD_K * 2) + ch * 16;
        size_t ga = (size_t)(m0 + row) * HD + ch * 8;
        *(uint4*)(smem + S2_A_HI + so) = *(const uint4*)(g_hr_hi + ga);
        *(uint4*)(smem + S2_A_LO + so) = *(const uint4*)(g_hr_lo + ga);
        int gn = n0 + row;
        uint4 bh = make_uint4(0, 0, 0, 0), bl = make_uint4(0, 0, 0, 0);
        if (gn < NNODES) {
            size_t gb = (size_t)gn * HD + ch * 8;
            bh = *(const uint4*)(g_z_hi + gb);
            bl = *(const uint4*)(g_z_lo + gb);
        }
        *(uint4*)(smem + S2_B_HI + so) = bh;
        *(uint4*)(smem + S2_B_LO + so) = bl;
    }
    __syncthreads();

    int wm = (wid & 1) * 64;        // warp m offset within tile
    int wn = (wid >> 1) * 32;       // warp n offset within tile
    int r8 = lid & 7, g = lid >> 3;

    uint32_t a_off = (uint32_t)((g & 1) * 8 + r8) * (PAD_K * 2) + (uint32_t)(g >> 1) * 16;
    uint32_t b_off = (uint32_t)((g >> 1) * 8 + r8) * (PAD_K * 2) + (uint32_t)(g & 1) * 16;

    float acc[4][4][4];
#pragma unroll
    for (int i = 0; i < 4; i++)
#pragma unroll
        for (int j = 0; j < 4; j++)
#pragma unroll
            for (int q = 0; q < 4; q++) acc[i][j][q] = 0.f;

    const uint32_t aBase[3] = { sb + S2_A_HI, sb + S2_A_HI, sb + S2_A_LO };
    const uint32_t bBase[3] = { sb + S2_B_HI, sb + S2_B_LO, sb + S2_B_HI };

#pragma unroll
    for (int pass = 0; pass < 3; pass++) {
        uint32_t aB = aBase[pass] + (uint32_t)wm * (PAD_K * 2) + a_off;
        uint32_t bB = bBase[pass] + (uint32_t)wn * (PAD_K * 2) + b_off;
#pragma unroll
        for (int kk = 0; kk < 8; kk++) {
            uint32_t af[4][4], bf[2][4];
#pragma unroll
            for (int mi = 0; mi < 4; mi++)
                ldsm_x4(aB + (uint32_t)mi * 16 * (PAD_K * 2) + kk * 32, af[mi]);
#pragma unroll
            for (int nj = 0; nj < 2; nj++)
                ldsm_x4(bB + (uint32_t)nj * 16 * (PAD_K * 2) + kk * 32, bf[nj]);
#pragma unroll
            for (int mi = 0; mi < 4; mi++) {
#pragma unroll
                for (int nf = 0; nf < 4; nf++)
                    mma_bf16(acc[mi][nf], af[mi], &bf[nf >> 1][(nf & 1) * 2]);
            }
        }
    }

    // ---- epilogue: direct stores ----
    int mrow = lid >> 2;            // 0..7
    int ncol = (lid & 3) * 2;       // 0,2,4,6
#pragma unroll
    for (int mi = 0; mi < 4; mi++) {
#pragma unroll
        for (int nf = 0; nf < 4; nf++) {
            int gm = m0 + wm + mi * 16 + mrow;
            int gn = n0 + wn + nf * 8 + ncol;
            if (gn < NNODES) {
                *(float2*)(C + (size_t)gm * NNODES + gn) =
                    make_float2(acc[mi][nf][0], acc[mi][nf][1]);
                *(float2*)(C + (size_t)(gm + 8) * NNODES + gn) =
                    make_float2(acc[mi][nf][2], acc[mi][nf][3]);
            }
        }
    }
}

// =================================================================
extern "C" void kernel_launch(void* const* d_in, const int* in_sizes, int n_in,
                              void* d_out, int out_size) {
    const int*   h        = (const int*)d_in[0];
    const int*   src      = (const int*)d_in[1];
    const int*   dst      = (const int*)d_in[2];
    const int*   etypes   = (const int*)d_in[3];
    const float* norm     = (const float*)d_in[4];
    const int*   head_ids = (const int*)d_in[5];
    const int*   rel_ids  = (const int*)d_in[6];
    const float* embed    = (const float*)d_in[7];
    const float* W1       = (const float*)d_in[8];
    const float* lw1      = (const float*)d_in[9];
    const float* b1       = (const float*)d_in[10];
    const float* W2       = (const float*)d_in[11];
    const float* lw2      = (const float*)d_in[12];
    const float* b2       = (const float*)d_in[13];
    const float* w_rel    = (const float*)d_in[14];
    const float* eps      = (const float*)d_in[15];
    float* out = (float*)d_out;

    const int E1_SMEM = NR * 64 * 16;   // 102400 B
    const int E2_SMEM = NR * 128 * 16;  // 204800 B
    cudaFuncSetAttribute(scores_mma_kernel,
                         cudaFuncAttributeMaxDynamicSharedMemorySize, S2_TOTAL);
    cudaFuncSetAttribute(edge1_kernel,
                         cudaFuncAttributeMaxDynamicSharedMemorySize, E1_SMEM);
    cudaFuncSetAttribute(edge2_kernel,
                         cudaFuncAttributeMaxDynamicSharedMemorySize, E2_SMEM);

    selfloop1_kernel<<<NNODES / 8, 128>>>(embed, h, lw1, b1);
    edge1_kernel<<<296, 512, E1_SMEM>>>(embed, h, src, dst, etypes, norm, W1);

    selfloop2_kernel<<<NNODES / 4, 256>>>(lw2, b2);
    edge2_kernel<<<148, 512, E2_SMEM>>>(src, dst, etypes, norm, W2);

    z_kernel<<<(NNODES * HD + 255) / 256, 256>>>(eps);

    hr_kernel<<<(NQ * HD + 255) / 256, 256>>>(head_ids, rel_ids, w_rel);

    dim3 grid((NNODES + TN - 1) / TN, NQ / TM);
    scores_mma_kernel<<<grid, 256, S2_TOTAL>>>(out);
}